// round 4
// baseline (speedup 1.0000x reference)
#include <cuda_runtime.h>

#define NQ   4096
#define NT   16      // number of j-tiles
#define TI   256     // i-tile = threads per block
#define TJ   256     // j-tile
#define TCAP 4       // per-(point, j-tile) neighbor cap
#define CCAP 8       // compact per-point neighbor cap

// Scratch (__device__ globals; no allocations). All partial arrays are fully
// overwritten each run -> no zeroing kernel, no atomics, deterministic.
__device__ float4         g_pt4[NQ];                  // {x, y, pE, pJ}
__device__ unsigned short g_rankP[2][NQ][NT];         // partial rank sums
__device__ unsigned char  g_cntP [2][NQ][NT];         // per-tile earlier-neighbor counts
__device__ unsigned short g_nbrP [2][NQ][NT][TCAP];   // per-tile earlier-neighbor ids
__device__ unsigned short g_nbrC [2][NQ][CCAP];       // compacted lists (built in k3)

// ---------------------------------------------------------------------------
// Per-point prep: 3-class softmax + point scaling. Deterministic across blocks.
// ---------------------------------------------------------------------------
__device__ __forceinline__ float4 prep_point(const float* __restrict__ logits,
                                             const float* __restrict__ boxes,
                                             float w, float h, int i, float* tgt) {
    float l0 = logits[3 * i + 0];
    float l1 = logits[3 * i + 1];
    float l2 = logits[3 * i + 2];
    float m  = fmaxf(l0, fmaxf(l1, l2));
    float e0 = expf(l0 - m);
    float e1 = expf(l1 - m);
    float e2 = expf(l2 - m);
    float s  = e0 + e1 + e2;
    float p0 = e0 / s;           // end_pt
    float p1 = e1 / s;           // junction_pt
    float p2 = e2 / s;           // background
    *tgt = 1.0f - p2;
    float x = boxes[2 * i + 0] * w;
    float y = boxes[2 * i + 1] * h;
    return make_float4(x, y, p0, p1);
}

// ---------------------------------------------------------------------------
// kA: fused prep + all-pairs. Block (bx,by): i in bx-tile vs j in by-tile.
// earlier(j,i) = bits(s_j) > bits(s_i) || (== && j < i)   (stable-sort order;
// softmax probs are nonneg finite -> IEEE bits are unsigned-order-monotone).
// Writes per-tile partial ranks and capped earlier-neighbor lists (no atomics).
// by==0 blocks also emit out[:,0..2] and g_pt4.
// ---------------------------------------------------------------------------
__global__ void kA_pairs(const float* __restrict__ logits,
                         const float* __restrict__ boxes,
                         const float* __restrict__ tsz,
                         float* __restrict__ out) {
    __shared__ float4 tile[TJ];   // {x, y, pE, pJ}

    int bx = blockIdx.x, by = blockIdx.y;
    int i  = bx * TI + threadIdx.x;
    int j0 = by * TJ;
    float w = tsz[0], h = tsz[1];

    float tgt_j;
    tile[threadIdx.x] = prep_point(logits, boxes, w, h, j0 + threadIdx.x, &tgt_j);
    float tgt_i;
    float4 me = prep_point(logits, boxes, w, h, i, &tgt_i);
    __syncthreads();

    if (by == 0) {
        out[5 * i + 0] = tgt_i;
        out[5 * i + 1] = me.x;
        out[5 * i + 2] = me.y;
        g_pt4[i] = me;
    }

    unsigned kE = __float_as_uint(me.z);
    unsigned kJ = __float_as_uint(me.w);
    int rE = 0, rJ = 0, cE = 0, cJ = 0;
    unsigned short nbE[TCAP], nbJ[TCAP];

#pragma unroll 8
    for (int jj = 0; jj < TJ; jj++) {
        float4 q = tile[jj];                 // single broadcast LDS.128
        int j = j0 + jj;
        float dx = me.x - q.x;
        float dy = me.y - q.y;
        // match non-contracted dx*dx + dy*dy evaluation
        float d2 = __fadd_rn(__fmul_rn(dx, dx), __fmul_rn(dy, dy));
        unsigned qE = __float_as_uint(q.z);
        unsigned qJ = __float_as_uint(q.w);
        bool lt = j < i;
        bool eE = (qE > kE) || ((qE == kE) && lt);
        bool eJ = (qJ > kJ) || ((qJ == kJ) && lt);
        rE += eE;
        rJ += eJ;
        if (d2 < 25.0f) {                    // rare (~0.03% of pairs)
            if (eE) { if (cE < TCAP) nbE[cE] = (unsigned short)j; cE++; }
            if (eJ) { if (cJ < TCAP) nbJ[cJ] = (unsigned short)j; cJ++; }
        }
    }

    g_rankP[0][i][by] = (unsigned short)rE;
    g_rankP[1][i][by] = (unsigned short)rJ;
    g_cntP[0][i][by]  = (unsigned char)min(cE, 255);
    g_cntP[1][i][by]  = (unsigned char)min(cJ, 255);
    int mE = min(cE, TCAP), mJ = min(cJ, TCAP);
    for (int k = 0; k < mE; k++) g_nbrP[0][i][by][k] = nbE[k];
    for (int k = 0; k < mJ; k++) g_nbrP[1][i][by][k] = nbJ[k];
}

// ---------------------------------------------------------------------------
// kB: gather compact neighbor lists, run greedy-NMS fixpoint on smem state,
// sum partial ranks, scatter out[:,3..4].
// earlier() is a strict total order => dependency DAG => chaotic sweeps
// converge to the unique greedy fixpoint; neighbor-list order irrelevant.
// ---------------------------------------------------------------------------
__global__ void kB_resolve(float* __restrict__ out) {
    __shared__ unsigned char keep [2][NQ];
    __shared__ unsigned char valid[2][NQ];
    __shared__ unsigned char cnt  [2][NQ];   // 255 = overflow -> full rescan
    __shared__ int changed;
    int tid = threadIdx.x;

    // --- gather: compact per-point neighbor lists, init keep/valid ---
    for (int u = tid; u < NQ; u += 1024) {
        float4 p = g_pt4[u];
        unsigned char vE = (p.z >= 0.05f) ? 1 : 0;
        unsigned char vJ = (p.w >= 0.05f) ? 1 : 0;
        valid[0][u] = vE; keep[0][u] = vE;
        valid[1][u] = vJ; keep[1][u] = vJ;
#pragma unroll
        for (int ch = 0; ch < 2; ch++) {
            uint4 cv = *(const uint4*)&g_cntP[ch][u][0];   // 16 count bytes
            if ((cv.x | cv.y | cv.z | cv.w) == 0u) { cnt[ch][u] = 0; continue; }
            const unsigned char* cb = (const unsigned char*)&cv;
            int pos = 0; bool ovf = false;
            for (int t = 0; t < NT; t++) {
                int c = cb[t];
                if (c > TCAP) { ovf = true; break; }
                for (int k = 0; k < c; k++) {
                    if (pos < CCAP) g_nbrC[ch][u][pos] = g_nbrP[ch][u][t][k];
                    pos++;
                }
            }
            cnt[ch][u] = (ovf || pos > CCAP) ? 255 : (unsigned char)pos;
        }
    }
    __syncthreads();   // also orders the g_nbrC global writes block-wide

    // --- fixpoint sweeps ---
    while (true) {
        if (tid == 0) changed = 0;
        __syncthreads();

        for (int ch = 0; ch < 2; ch++) {
            for (int u = tid; u < NQ; u += 1024) {
                int c = cnt[ch][u];
                if (c == 0) continue;                 // value can never change
                bool nk = valid[ch][u];
                if (nk) {
                    if (c != 255) {
                        for (int k = 0; k < c; k++) {
                            if (keep[ch][g_nbrC[ch][u][k]]) { nk = false; break; }
                        }
                    } else {
                        // overflow fallback: full rescan (never hit on this data)
                        float4 me = g_pt4[u];
                        float si = (ch == 0) ? me.z : me.w;
                        for (int j = 0; j < NQ && nk; j++) {
                            float4 q = g_pt4[j];
                            float sj = (ch == 0) ? q.z : q.w;
                            bool e = (sj > si) || ((sj == si) && (j < u));
                            if (e && keep[ch][j]) {
                                float dx = me.x - q.x, dy = me.y - q.y;
                                float d2 = __fadd_rn(__fmul_rn(dx, dx), __fmul_rn(dy, dy));
                                if (d2 < 25.0f) nk = false;
                            }
                        }
                    }
                }
                if (nk != (bool)keep[ch][u]) {
                    keep[ch][u] = nk ? 1 : 0;
                    changed = 1;
                }
            }
        }
        __syncthreads();
        if (changed == 0) break;
        __syncthreads();   // all threads observed 'changed' before tid0 resets
    }

    // --- scatter: slot(u) = sum of 16 partial ranks ---
    for (int u = tid; u < NQ; u += 1024) {
        float4 p = g_pt4[u];
#pragma unroll
        for (int ch = 0; ch < 2; ch++) {
            const uint4* rp = (const uint4*)&g_rankP[ch][u][0];
            uint4 a = rp[0], b = rp[1];
            unsigned s = 0;
            s += (a.x & 0xffffu) + (a.x >> 16) + (a.y & 0xffffu) + (a.y >> 16);
            s += (a.z & 0xffffu) + (a.z >> 16) + (a.w & 0xffffu) + (a.w >> 16);
            s += (b.x & 0xffffu) + (b.x >> 16) + (b.y & 0xffffu) + (b.y >> 16);
            s += (b.z & 0xffffu) + (b.z >> 16) + (b.w & 0xffffu) + (b.w >> 16);
            float sc = (ch == 0) ? p.z : p.w;
            out[s * 5 + 3 + ch] = keep[ch][u] ? sc : 0.0f;
        }
    }
}

// ---------------------------------------------------------------------------
extern "C" void kernel_launch(void* const* d_in, const int* in_sizes, int n_in,
                              void* d_out, int out_size) {
    const float* logits = (const float*)d_in[0];  // [1,4096,3]
    const float* boxes  = (const float*)d_in[1];  // [1,4096,2]
    // d_in[2] = pred_gids (unused)
    const float* tsz    = (const float*)d_in[3];  // [1,2]
    float* out          = (float*)d_out;          // [1,4096,5]

    dim3 gA(NQ / TI, NQ / TJ);
    kA_pairs<<<gA, TI>>>(logits, boxes, tsz, out);
    kB_resolve<<<1, 1024>>>(out);
}

// round 5
// speedup vs baseline: 1.4811x; 1.4811x over previous
#include <cuda_runtime.h>

#define NQ   4096
#define NT   16      // number of j-tiles
#define TI   256     // i-tile = threads per block
#define TJ   256     // j-tile
#define TCAP 4       // per-(point, j-tile) neighbor cap
#define CCAP 8       // compact per-point neighbor cap

// Scratch (__device__ globals; no allocations). Everything is fully
// overwritten each run -> deterministic, no zeroing, no atomics.
__device__ float4         g_pt4[NQ];                  // {x, y, pE, pJ}
__device__ unsigned short g_rankP[2][NQ][NT];         // partial rank sums
__device__ unsigned char  g_cntP [2][NQ][NT];         // per-tile neighbor counts
__device__ unsigned short g_nbrP [2][NQ][NT][TCAP];   // per-tile neighbor ids
__device__ unsigned short g_slot [2][NQ];             // final output slot (rank)
__device__ unsigned char  g_cntC [2][NQ];             // compact count (255=overflow)
__device__ unsigned short g_nbrC [2][NQ][CCAP];       // compact neighbor lists

// ---------------------------------------------------------------------------
// Per-point prep: 3-class softmax + point scaling. Deterministic across blocks.
// ---------------------------------------------------------------------------
__device__ __forceinline__ float4 prep_point(const float* __restrict__ logits,
                                             const float* __restrict__ boxes,
                                             float w, float h, int i, float* tgt) {
    float l0 = logits[3 * i + 0];
    float l1 = logits[3 * i + 1];
    float l2 = logits[3 * i + 2];
    float m  = fmaxf(l0, fmaxf(l1, l2));
    float e0 = expf(l0 - m);
    float e1 = expf(l1 - m);
    float e2 = expf(l2 - m);
    float s  = e0 + e1 + e2;
    float p0 = e0 / s;           // end_pt
    float p1 = e1 / s;           // junction_pt
    float p2 = e2 / s;           // background
    *tgt = 1.0f - p2;
    float x = boxes[2 * i + 0] * w;
    float y = boxes[2 * i + 1] * h;
    return make_float4(x, y, p0, p1);
}

// ---------------------------------------------------------------------------
// kA: fused prep + all-pairs. Block (bx,by): i in bx-tile vs j in by-tile.
// earlier(j,i) = bits(s_j) > bits(s_i) || (== && j < i)   (stable-sort order;
// softmax probs are nonneg finite -> IEEE bits are unsigned-order-monotone).
// ---------------------------------------------------------------------------
__global__ void kA_pairs(const float* __restrict__ logits,
                         const float* __restrict__ boxes,
                         const float* __restrict__ tsz,
                         float* __restrict__ out) {
    __shared__ float4 tile[TJ];   // {x, y, pE, pJ}

    int bx = blockIdx.x, by = blockIdx.y;
    int i  = bx * TI + threadIdx.x;
    int j0 = by * TJ;
    float w = tsz[0], h = tsz[1];

    float tgt_j;
    tile[threadIdx.x] = prep_point(logits, boxes, w, h, j0 + threadIdx.x, &tgt_j);
    float tgt_i;
    float4 me = prep_point(logits, boxes, w, h, i, &tgt_i);
    __syncthreads();

    if (by == 0) {
        out[5 * i + 0] = tgt_i;
        out[5 * i + 1] = me.x;
        out[5 * i + 2] = me.y;
        g_pt4[i] = me;
    }

    unsigned kE = __float_as_uint(me.z);
    unsigned kJ = __float_as_uint(me.w);
    int rE = 0, rJ = 0, cE = 0, cJ = 0;
    unsigned short nbE[TCAP], nbJ[TCAP];

#pragma unroll 8
    for (int jj = 0; jj < TJ; jj++) {
        float4 q = tile[jj];                 // single broadcast LDS.128
        int j = j0 + jj;
        float dx = me.x - q.x;
        float dy = me.y - q.y;
        // match non-contracted dx*dx + dy*dy evaluation
        float d2 = __fadd_rn(__fmul_rn(dx, dx), __fmul_rn(dy, dy));
        unsigned qE = __float_as_uint(q.z);
        unsigned qJ = __float_as_uint(q.w);
        bool lt = j < i;
        bool eE = (qE > kE) || ((qE == kE) && lt);
        bool eJ = (qJ > kJ) || ((qJ == kJ) && lt);
        rE += eE;
        rJ += eJ;
        if (d2 < 25.0f) {                    // rare (~0.03% of pairs)
            if (eE) { if (cE < TCAP) nbE[cE] = (unsigned short)j; cE++; }
            if (eJ) { if (cJ < TCAP) nbJ[cJ] = (unsigned short)j; cJ++; }
        }
    }

    g_rankP[0][i][by] = (unsigned short)rE;
    g_rankP[1][i][by] = (unsigned short)rJ;
    g_cntP[0][i][by]  = (unsigned char)min(cE, 255);
    g_cntP[1][i][by]  = (unsigned char)min(cJ, 255);
    int mE = min(cE, TCAP), mJ = min(cJ, TCAP);
    for (int k = 0; k < mE; k++) g_nbrP[0][i][by][k] = nbE[k];
    for (int k = 0; k < mJ; k++) g_nbrP[1][i][by][k] = nbJ[k];
}

// ---------------------------------------------------------------------------
// kG: per-point compaction (full-chip parallel, one thread per point).
//   slot(u) = sum of 16 partial ranks; compact neighbor list <= CCAP (255=ovf)
// ---------------------------------------------------------------------------
__global__ void kG_gather() {
    int u = blockIdx.x * blockDim.x + threadIdx.x;
    if (u >= NQ) return;
#pragma unroll
    for (int ch = 0; ch < 2; ch++) {
        // rank sum
        const uint4* rp = (const uint4*)&g_rankP[ch][u][0];
        uint4 a = rp[0], b = rp[1];
        unsigned s = 0;
        s += (a.x & 0xffffu) + (a.x >> 16) + (a.y & 0xffffu) + (a.y >> 16);
        s += (a.z & 0xffffu) + (a.z >> 16) + (a.w & 0xffffu) + (a.w >> 16);
        s += (b.x & 0xffffu) + (b.x >> 16) + (b.y & 0xffffu) + (b.y >> 16);
        s += (b.z & 0xffffu) + (b.z >> 16) + (b.w & 0xffffu) + (b.w >> 16);
        g_slot[ch][u] = (unsigned short)s;

        // neighbor compaction
        uint4 cv = *(const uint4*)&g_cntP[ch][u][0];
        if ((cv.x | cv.y | cv.z | cv.w) == 0u) { g_cntC[ch][u] = 0; continue; }
        const unsigned char* cb = (const unsigned char*)&cv;
        int pos = 0; bool ovf = false;
        for (int t = 0; t < NT; t++) {
            int c = cb[t];
            if (c == 0) continue;
            if (c > TCAP) { ovf = true; break; }
            for (int k = 0; k < c; k++) {
                if (pos < CCAP) g_nbrC[ch][u][pos] = g_nbrP[ch][u][t][k];
                pos++;
            }
        }
        g_cntC[ch][u] = (ovf || pos > CCAP) ? 255 : (unsigned char)pos;
    }
}

// ---------------------------------------------------------------------------
// kR: greedy-NMS fixpoint + scatter. Single block; per-thread unit state
// (cnt, valid, score, first neighbor) register-resident; keep[] in smem.
// earlier() is a strict total order => dependency DAG => chaotic sweeps
// converge to the unique greedy fixpoint.
// ---------------------------------------------------------------------------
__global__ void kR_resolve(float* __restrict__ out) {
    __shared__ unsigned char keep[2][NQ];
    __shared__ int changed;
    int tid = threadIdx.x;

    // per-thread units: u = tid + k*1024, k in [0,4), ch in {0,1}
    float         sc   [4][2];
    unsigned char vld  [4][2];
    unsigned char cnt  [4][2];
    unsigned short nb0 [4][2];

#pragma unroll
    for (int k = 0; k < 4; k++) {
        int u = tid + k * 1024;
        float4 p = g_pt4[u];
        sc[k][0] = p.z;  sc[k][1] = p.w;
        vld[k][0] = (p.z >= 0.05f) ? 1 : 0;
        vld[k][1] = (p.w >= 0.05f) ? 1 : 0;
        keep[0][u] = vld[k][0];
        keep[1][u] = vld[k][1];
#pragma unroll
        for (int ch = 0; ch < 2; ch++) {
            unsigned char c = g_cntC[ch][u];
            if (!vld[k][ch]) c = 0;       // kept==0 forever; nothing to sweep
            cnt[k][ch] = c;
            nb0[k][ch] = (c >= 1 && c != 255) ? g_nbrC[ch][u][0] : 0;
        }
    }
    __syncthreads();

    // fixpoint sweeps
    while (true) {
        if (tid == 0) changed = 0;
        __syncthreads();

        bool any = false;
#pragma unroll
        for (int k = 0; k < 4; k++) {
#pragma unroll
            for (int ch = 0; ch < 2; ch++) {
                int c = cnt[k][ch];
                if (c == 0) continue;
                int u = tid + k * 1024;
                bool nk;
                if (c == 1) {
                    nk = !keep[ch][nb0[k][ch]];
                } else if (c != 255) {
                    nk = !keep[ch][nb0[k][ch]];
                    for (int kk = 1; kk < c && nk; kk++)
                        nk = !keep[ch][g_nbrC[ch][u][kk]];
                } else {
                    // overflow fallback: exact rescan (P ~ 1e-9; correctness only)
                    float4 me = g_pt4[u];
                    float si = sc[k][ch];
                    nk = true;
                    for (int j = 0; j < NQ && nk; j++) {
                        float4 q = g_pt4[j];
                        float sj = (ch == 0) ? q.z : q.w;
                        bool e = (sj > si) || ((sj == si) && (j < u));
                        if (e && keep[ch][j]) {
                            float dx = me.x - q.x, dy = me.y - q.y;
                            float d2 = __fadd_rn(__fmul_rn(dx, dx), __fmul_rn(dy, dy));
                            if (d2 < 25.0f) nk = false;
                        }
                    }
                }
                if (nk != (bool)keep[ch][u]) {
                    keep[ch][u] = nk ? 1 : 0;
                    any = true;
                }
            }
        }
        if (any) changed = 1;
        __syncthreads();
        if (changed == 0) break;
        __syncthreads();   // all threads observed 'changed' before tid0 resets
    }

    // scatter NMS outputs to sorted slots
#pragma unroll
    for (int k = 0; k < 4; k++) {
        int u = tid + k * 1024;
#pragma unroll
        for (int ch = 0; ch < 2; ch++) {
            unsigned s = g_slot[ch][u];
            out[s * 5 + 3 + ch] = keep[ch][u] ? sc[k][ch] : 0.0f;
        }
    }
}

// ---------------------------------------------------------------------------
extern "C" void kernel_launch(void* const* d_in, const int* in_sizes, int n_in,
                              void* d_out, int out_size) {
    const float* logits = (const float*)d_in[0];  // [1,4096,3]
    const float* boxes  = (const float*)d_in[1];  // [1,4096,2]
    // d_in[2] = pred_gids (unused)
    const float* tsz    = (const float*)d_in[3];  // [1,2]
    float* out          = (float*)d_out;          // [1,4096,5]

    dim3 gA(NQ / TI, NQ / TJ);
    kA_pairs<<<gA, TI>>>(logits, boxes, tsz, out);
    kG_gather<<<NQ / 256, 256>>>();
    kR_resolve<<<1, 1024>>>(out);
}